// round 5
// baseline (speedup 1.0000x reference)
#include <cuda_runtime.h>
#include <cuda_fp16.h>
#include <math.h>
#include <stdint.h>

#define B_ 2
#define T_ 4096
#define E_ 2048
#define E2_ 4096
#define H_ 16
#define KD_ 128
#define HD_ 256
#define CH_ 256
#define NC_ 16
#define NCHUNKS (B_*NC_*H_)   // 512

// ================= scratch =================
__device__ float g_q [B_*T_*E_];
__device__ float g_k [B_*T_*E_];
__device__ float g_v [B_*T_*E2_];
__device__ float g_gt[B_*T_*E2_];
__device__ float g_qk[(size_t)NCHUNKS*CH_*CH_];
__device__ float g_isc[NCHUNKS*CH_];
__device__ float g_inner[(size_t)NCHUNKS*CH_*HD_];
__device__ float g_kv [(size_t)NCHUNKS*KD_*HD_];
__device__ float g_kvr[(size_t)NCHUNKS*KD_*HD_];
__device__ float g_csc[NCHUNKS*HD_];
// half-precision staging
__device__ __half g_xh [B_*T_*E_];
__device__ __half g_roh[B_*T_*E2_];
__device__ __half g_wqh[E_*E_];
__device__ __half g_wkh[E_*E_];
__device__ __half g_wvh[(size_t)E2_*E_];
__device__ __half g_wgh[(size_t)E2_*E_];
__device__ __half g_woh[(size_t)E_*E2_];

// ================= helpers =================
__device__ __forceinline__ uint32_t smem_u32(const void* p) {
    uint32_t a;
    asm("{ .reg .u64 t; cvta.to.shared.u64 t, %1; cvt.u32.u64 %0, t; }" : "=r"(a) : "l"(p));
    return a;
}
__device__ __forceinline__ void cp16(uint32_t dst, const void* src) {
    asm volatile("cp.async.cg.shared.global [%0], [%1], 16;" :: "r"(dst), "l"(src));
}
__device__ __forceinline__ void cp_commit() { asm volatile("cp.async.commit_group;"); }
__device__ __forceinline__ void ldm_x4(uint32_t r[4], uint32_t addr) {
    asm volatile("ldmatrix.sync.aligned.m8n8.x4.shared.b16 {%0,%1,%2,%3}, [%4];"
        : "=r"(r[0]), "=r"(r[1]), "=r"(r[2]), "=r"(r[3]) : "r"(addr));
}
__device__ __forceinline__ void mma_f16(float c[4], const uint32_t a[4], const uint32_t b[2]) {
    asm volatile(
        "mma.sync.aligned.m16n8k16.row.col.f32.f16.f16.f32 "
        "{%0,%1,%2,%3}, {%4,%5,%6,%7}, {%8,%9}, {%0,%1,%2,%3};"
        : "+f"(c[0]), "+f"(c[1]), "+f"(c[2]), "+f"(c[3])
        : "r"(a[0]), "r"(a[1]), "r"(a[2]), "r"(a[3]), "r"(b[0]), "r"(b[1]));
}

// ================= f32 -> f16 converter =================
__global__ void f2h(const float* __restrict__ in, __half* __restrict__ out, int n4)
{
    int i = blockIdx.x * blockDim.x + threadIdx.x;
    if (i >= n4) return;
    float4 v = *(const float4*)(in + (size_t)i * 4);
    __half2 h[2];
    h[0] = __floats2half2_rn(v.x, v.y);
    h[1] = __floats2half2_rn(v.z, v.w);
    *(uint2*)(out + (size_t)i * 4) = *(uint2*)h;
}

// ===== fp16 tensor-core GEMM: C = rot?((A @ W^T + bias) * scale) =====
// Block 128(M) x 256(N), BK=32, 3 stages. 8 warps 2(M) x 4(N), warp tile 64x64.
// SMEM stage: A 128x40h (10240 B) + B 256x40h (20480 B) = 30720 B; x3 = 92160 B.
#define STG_BYTES 30720
#define B_OFF 10240
#define GEMMH_SMEM (3*STG_BYTES)

__global__ void __launch_bounds__(256, 1)
gemm_h(const __half* __restrict__ A, const __half* __restrict__ W,
       const float* __restrict__ bias, float* __restrict__ C,
       int K, int Ncols, float scale, int rot,
       const float* __restrict__ sn, const float* __restrict__ cs)
{
    extern __shared__ __align__(128) char smh[];
    const int tid = threadIdx.x;
    const int wid = tid >> 5, lane = tid & 31;
    const int wm = wid & 1, wn = wid >> 1;
    const int g = lane >> 2, q = lane & 3;
    const int bx = blockIdx.x, by = blockIdx.y;

    const __half* Ab = A + (size_t)(by * 128) * K;
    const __half* Wb = W + (size_t)(bx * 256) * K;
    const uint32_t sb = smem_u32(smh);

    // loaders: A: thread t -> row t>>1, 32B half-row (2 cp16); B: row t, 64B (4 cp16)
    const int a_row = tid >> 1;
    const int a_cb  = (tid & 1) * 32;   // byte offset in row

    const int lrow8 = (lane & 7) + ((lane >> 3) & 1) * 8;
    const int koffB = (lane >> 4) * 16;

    float acc[4][8][4] = {};
    const int NS = K / 32;

    // prologue: slabs 0,1 -> stages 0,1
    #pragma unroll
    for (int s = 0; s < 2; s++) {
        uint32_t stg = sb + (uint32_t)s * STG_BYTES;
        const __half* As = Ab + (size_t)a_row * K + s * 32 + (a_cb >> 1);
        cp16(stg + a_row * 80 + a_cb, As);
        cp16(stg + a_row * 80 + a_cb + 16, As + 8);
        const __half* Ws = Wb + (size_t)tid * K + s * 32;
        #pragma unroll
        for (int u = 0; u < 4; u++)
            cp16(stg + B_OFF + tid * 80 + u * 16, Ws + u * 8);
        cp_commit();
    }

    for (int s = 0; s < NS; s++) {
        asm volatile("cp.async.wait_group 1;");
        __syncthreads();
        // prefetch slab s+2
        if (s + 2 < NS) {
            uint32_t stg = sb + (uint32_t)((s + 2) % 3) * STG_BYTES;
            const __half* As = Ab + (size_t)a_row * K + (s + 2) * 32 + (a_cb >> 1);
            cp16(stg + a_row * 80 + a_cb, As);
            cp16(stg + a_row * 80 + a_cb + 16, As + 8);
            const __half* Ws = Wb + (size_t)tid * K + (s + 2) * 32;
            #pragma unroll
            for (int u = 0; u < 4; u++)
                cp16(stg + B_OFF + tid * 80 + u * 16, Ws + u * 8);
        }
        cp_commit();

        const uint32_t stg = sb + (uint32_t)(s % 3) * STG_BYTES;
        const uint32_t a_base = stg + (uint32_t)((wm * 64 + lrow8) * 80 + koffB);
        const uint32_t b_base = stg + B_OFF + (uint32_t)((wn * 64 + lrow8) * 80 + koffB);
        #pragma unroll
        for (int ks = 0; ks < 2; ks++) {
            const uint32_t kb = ks * 32;
            uint32_t af[4][4];
            #pragma unroll
            for (int mf = 0; mf < 4; mf++) ldm_x4(af[mf], a_base + mf * 16 * 80 + kb);
            uint32_t bf[8][2];
            #pragma unroll
            for (int nf2 = 0; nf2 < 4; nf2++) {
                uint32_t t4[4];
                ldm_x4(t4, b_base + nf2 * 16 * 80 + kb);
                bf[2*nf2  ][0] = t4[0]; bf[2*nf2  ][1] = t4[2];
                bf[2*nf2+1][0] = t4[1]; bf[2*nf2+1][1] = t4[3];
            }
            #pragma unroll
            for (int mf = 0; mf < 4; mf++)
                #pragma unroll
                for (int nf = 0; nf < 8; nf++)
                    mma_f16(acc[mf][nf], af[mf], bf[nf]);
        }
    }

    // epilogue: bias + scale (+ rotary)
    #pragma unroll
    for (int mf = 0; mf < 4; mf++) {
        #pragma unroll
        for (int nf = 0; nf < 8; nf++) {
            const int row = by * 128 + wm * 64 + mf * 16 + g;
            const int col = bx * 256 + wn * 64 + nf * 8 + q * 2;
            const float b0 = bias[col], b1 = bias[col + 1];
            float2 o0, o1;
            o0.x = (acc[mf][nf][0] + b0) * scale;
            o0.y = (acc[mf][nf][1] + b1) * scale;
            o1.x = (acc[mf][nf][2] + b0) * scale;
            o1.y = (acc[mf][nf][3] + b1) * scale;
            if (rot) {
                const int d = col & (KD_ - 1);
                const int t0 = row & (T_ - 1);
                const int t1 = t0 + 8;
                float c0 = cs[t0*KD_ + d], c1 = cs[t0*KD_ + d + 1];
                float s0 = sn[t0*KD_ + d], s1 = sn[t0*KD_ + d + 1];
                float r0x = o0.x * c0 - o0.y * s0;
                float r0y = o0.y * c1 + o0.x * s1;
                o0.x = r0x; o0.y = r0y;
                c0 = cs[t1*KD_ + d]; c1 = cs[t1*KD_ + d + 1];
                s0 = sn[t1*KD_ + d]; s1 = sn[t1*KD_ + d + 1];
                float r1x = o1.x * c0 - o1.y * s0;
                float r1y = o1.y * c1 + o1.x * s1;
                o1.x = r1x; o1.y = r1y;
            }
            *(float2*)(C + (size_t)row * Ncols + col) = o0;
            *(float2*)(C + (size_t)(row + 8) * Ncols + col) = o1;
        }
    }
}

// ================= fp32 8x8 microkernel step (float4 LDS) =================
__device__ __forceinline__ void mk_step(const float* a, const float* b, float acc[8][8]) {
    float rm[8], rn[8];
    *(float4*)&rm[0] = *(const float4*)(a);
    *(float4*)&rm[4] = *(const float4*)(a + 4);
    *(float4*)&rn[0] = *(const float4*)(b);
    *(float4*)&rn[4] = *(const float4*)(b + 4);
    #pragma unroll
    for (int i = 0; i < 8; i++)
        #pragma unroll
        for (int j = 0; j < 8; j++)
            acc[i][j] += rm[i] * rn[j];
}

// ---------------- qk = qr @ kr^T * mask, plus row |.| sums ----------------
__global__ __launch_bounds__(512)
void qk_kernel(const float* __restrict__ mask)
{
    __shared__ float As[8][128];
    __shared__ float Bs[8][256];
    const int z = blockIdx.x;
    const int chunk = z >> 1, half = z & 1;
    const int b = chunk / (NC_*H_);
    const int n = (chunk / H_) % NC_;
    const int h = chunk % H_;
    const int row0 = half * 128;
    const int tid = threadIdx.x;
    const int tr = tid >> 5, tc = tid & 31;
    const float* Ab = g_q + ((size_t)(b*T_ + n*CH_ + row0)) * E_ + h*KD_;
    const float* Bb = g_k + ((size_t)(b*T_ + n*CH_)) * E_ + h*KD_;
    const int a_row = tid >> 2, a_k = (tid & 3) * 2;
    const int b_row = tid >> 1, b_k = (tid & 1) * 4;
    float acc[8][8] = {};
    for (int k0 = 0; k0 < KD_; k0 += 8) {
        float2 a2 = *(const float2*)(Ab + (size_t)a_row * E_ + k0 + a_k);
        float4 b4 = *(const float4*)(Bb + (size_t)b_row * E_ + k0 + b_k);
        As[a_k  ][a_row] = a2.x;
        As[a_k+1][a_row] = a2.y;
        Bs[b_k+0][b_row] = b4.x; Bs[b_k+1][b_row] = b4.y;
        Bs[b_k+2][b_row] = b4.z; Bs[b_k+3][b_row] = b4.w;
        __syncthreads();
        #pragma unroll
        for (int kk = 0; kk < 8; kk++) mk_step(&As[kk][tr*8], &Bs[kk][tc*8], acc);
        __syncthreads();
    }
    float* qko = g_qk + (size_t)chunk * (CH_*CH_) + (size_t)row0 * CH_;
    const float* mrow = mask + (size_t)h * (CH_*CH_) + (size_t)row0 * CH_;
    #pragma unroll
    for (int i = 0; i < 8; i++) {
        int r = tr*8 + i;
        float psum = 0.f;
        #pragma unroll
        for (int j = 0; j < 8; j++) {
            int c = tc*8 + j;
            float v = acc[i][j] * mrow[(size_t)r*CH_ + c];
            qko[(size_t)r*CH_ + c] = v;
            psum += fabsf(v);
        }
        #pragma unroll
        for (int o = 16; o > 0; o >>= 1)
            psum += __shfl_xor_sync(0xffffffffu, psum, o);
        if (tc == 0) g_isc[chunk*CH_ + row0 + r] = psum;
    }
}

// ---------------- inner = (qk / clip(isc,1)) @ vc ----------------
__global__ __launch_bounds__(512)
void inner_kernel()
{
    __shared__ float As[8][128];
    __shared__ float Bs[8][256];
    const int z = blockIdx.x;
    const int chunk = z >> 1, half = z & 1;
    const int b = chunk / (NC_*H_);
    const int n = (chunk / H_) % NC_;
    const int h = chunk % H_;
    const int row0 = half * 128;
    const int tid = threadIdx.x;
    const int tr = tid >> 5, tc = tid & 31;
    const float* Ab = g_qk + (size_t)chunk * (CH_*CH_) + (size_t)row0 * CH_;
    const float* Vb = g_v + ((size_t)(b*T_ + n*CH_)) * E2_ + h*HD_;
    const int a_row = tid >> 2, a_k = (tid & 3) * 2;
    const int bkk = tid >> 6, bv = (tid & 63) * 4;
    float acc[8][8] = {};
    for (int k0 = 0; k0 < CH_; k0 += 8) {
        float2 a2 = *(const float2*)(Ab + (size_t)a_row * CH_ + k0 + a_k);
        As[a_k  ][a_row] = a2.x;
        As[a_k+1][a_row] = a2.y;
        float4 b4 = *(const float4*)(Vb + (size_t)(k0 + bkk) * E2_ + bv);
        *(float4*)&Bs[bkk][bv] = b4;
        __syncthreads();
        #pragma unroll
        for (int kk = 0; kk < 8; kk++) mk_step(&As[kk][tr*8], &Bs[kk][tc*8], acc);
        __syncthreads();
    }
    float* op = g_inner + (size_t)chunk * (CH_*HD_) + (size_t)row0 * HD_;
    #pragma unroll
    for (int i = 0; i < 8; i++) {
        int r = tr*8 + i;
        float inv = 1.f / fmaxf(g_isc[chunk*CH_ + row0 + r], 1.f);
        #pragma unroll
        for (int j = 0; j < 8; j++)
            op[(size_t)r*HD_ + tc*8 + j] = acc[i][j] * inv;
    }
}

// ---------------- kv[k,v] = sum_c kr[c,k]*maskrow[c]*vc[c,v] ----------------
__global__ __launch_bounds__(512)
void kv_kernel(const float* __restrict__ mask)
{
    __shared__ float As[8][128];
    __shared__ float Bs[8][256];
    const int chunk = blockIdx.x;
    const int b = chunk / (NC_*H_);
    const int n = (chunk / H_) % NC_;
    const int h = chunk % H_;
    const int tid = threadIdx.x;
    const int tr = tid >> 5, tc = tid & 31;
    const float* Kb = g_k + ((size_t)(b*T_ + n*CH_)) * E_ + h*KD_;
    const float* Vb = g_v + ((size_t)(b*T_ + n*CH_)) * E2_ + h*HD_;
    const float* wrow = mask + (size_t)h * (CH_*CH_) + (size_t)(CH_-1) * CH_;
    const int acc_cc = tid >> 6;
    const int a_kcol = (tid & 63) * 2;
    const int b_vcol = (tid & 63) * 4;
    float acc[8][8] = {};
    for (int c0 = 0; c0 < CH_; c0 += 8) {
        float w = wrow[c0 + acc_cc];
        float2 a2 = *(const float2*)(Kb + (size_t)(c0 + acc_cc) * E_ + a_kcol);
        As[acc_cc][a_kcol  ] = a2.x * w;
        As[acc_cc][a_kcol+1] = a2.y * w;
        float4 b4 = *(const float4*)(Vb + (size_t)(c0 + acc_cc) * E2_ + b_vcol);
        *(float4*)&Bs[acc_cc][b_vcol] = b4;
        __syncthreads();
        #pragma unroll
        for (int kk = 0; kk < 8; kk++) mk_step(&As[kk][tr*8], &Bs[kk][tc*8], acc);
        __syncthreads();
    }
    float* op = g_kv + (size_t)chunk * (KD_*HD_);
    #pragma unroll
    for (int i = 0; i < 8; i++)
        #pragma unroll
        for (int j = 0; j < 8; j++)
            op[(size_t)(tr*8+i)*HD_ + tc*8 + j] = acc[i][j];
}

// ---------------- cross-chunk scan ----------------
__global__ __launch_bounds__(256)
void scan_kernel(const float* __restrict__ cdec)
{
    const int vb = blockIdx.x & 15;
    const int bh = blockIdx.x >> 4;
    const int b = bh / H_, h = bh % H_;
    const int v0 = vb * 16;
    const int tid = threadIdx.x;
    const int v = tid & 15;
    const int kg = tid >> 4;
    float s[8] = {0,0,0,0,0,0,0,0};
    __shared__ float sc[16];
    __shared__ float red[256];
    if (tid < 16) sc[tid] = 1.f;
    __syncthreads();
    const float cd = cdec[h];
    for (int n = 0; n < NC_; n++) {
        const int chunk = (b*NC_ + n)*H_ + h;
        const size_t zo = (size_t)chunk * (KD_*HD_);
        float invsc = 1.f / sc[v];
        #pragma unroll
        for (int i = 0; i < 8; i++)
            g_kvr[zo + (size_t)(kg*8+i)*HD_ + v0 + v] = s[i] * invsc;
        if (tid < 16) g_csc[chunk*HD_ + v0 + tid] = sc[tid];
        float p = 0.f;
        #pragma unroll
        for (int i = 0; i < 8; i++) {
            s[i] = s[i]*cd + g_kv[zo + (size_t)(kg*8+i)*HD_ + v0 + v];
            p += fabsf(s[i]);
        }
        red[tid] = p;
        __syncthreads();
        if (tid < 16) {
            float sum = 0.f;
            #pragma unroll
            for (int j = 0; j < 16; j++) sum += red[j*16 + tid];
            sc[tid] = fmaxf(sum, 1.f);
        }
        __syncthreads();
    }
}

// ------- cross = (qr*idec) @ kv_rec; combine + LN + silu(g) gate -> half -------
__global__ __launch_bounds__(512)
void cross_kernel(const float* __restrict__ idec)
{
    __shared__ float As[8][128];
    __shared__ float Bs[8][256];
    const int z = blockIdx.x;
    const int chunk = z >> 1, half = z & 1;
    const int b = chunk / (NC_*H_);
    const int n = (chunk / H_) % NC_;
    const int h = chunk % H_;
    const int row0 = half * 128;
    const int tid = threadIdx.x;
    const int tr = tid >> 5, tc = tid & 31;
    const float* Ab = g_q + ((size_t)(b*T_ + n*CH_ + row0)) * E_ + h*KD_;
    const float* Bb = g_kvr + (size_t)chunk * (KD_*HD_);
    const int a_row = tid >> 2, a_k = (tid & 3) * 2;
    const int bkk = tid >> 6, bv = (tid & 63) * 4;
    const float aw = idec[h*CH_ + row0 + a_row];
    float acc[8][8] = {};
    for (int k0 = 0; k0 < KD_; k0 += 8) {
        float2 a2 = *(const float2*)(Ab + (size_t)a_row * E_ + k0 + a_k);
        As[a_k  ][a_row] = a2.x * aw;
        As[a_k+1][a_row] = a2.y * aw;
        float4 b4 = *(const float4*)(Bb + (size_t)(k0 + bkk) * HD_ + bv);
        *(float4*)&Bs[bkk][bv] = b4;
        __syncthreads();
        #pragma unroll
        for (int kk = 0; kk < 8; kk++) mk_step(&As[kk][tr*8], &Bs[kk][tc*8], acc);
        __syncthreads();
    }
    const float* innp = g_inner + (size_t)chunk * (CH_*HD_) + (size_t)row0 * HD_;
    const float* cscp = g_csc + chunk*HD_;
    const float* gp   = g_gt + ((size_t)(b*T_ + n*CH_ + row0)) * E2_ + h*HD_;
    __half* rop       = g_roh + ((size_t)(b*T_ + n*CH_ + row0)) * E2_ + h*HD_;
    #pragma unroll
    for (int i = 0; i < 8; i++) {
        int r = tr*8 + i;
        float isc = fmaxf(g_isc[chunk*CH_ + row0 + r], 1.f);
        float rsum = 0.f, rsq = 0.f;
        #pragma unroll
        for (int j = 0; j < 8; j++) {
            int c = tc*8 + j;
            float o = innp[(size_t)r*HD_ + c] / cscp[c] + acc[i][j] / isc;
            acc[i][j] = o;
            rsum += o;
            rsq  += o*o;
        }
        #pragma unroll
        for (int off = 16; off > 0; off >>= 1) {
            rsum += __shfl_xor_sync(0xffffffffu, rsum, off);
            rsq  += __shfl_xor_sync(0xffffffffu, rsq,  off);
        }
        float mean = rsum * (1.f/HD_);
        float var  = rsq  * (1.f/HD_) - mean*mean;
        float rstd = rsqrtf(var + 1e-5f);
        __half2 hv[4];
        #pragma unroll
        for (int j = 0; j < 8; j += 2) {
            int c = tc*8 + j;
            float gv0 = gp[(size_t)r*E2_ + c];
            float gv1 = gp[(size_t)r*E2_ + c + 1];
            float o0 = (gv0 / (1.f + expf(-gv0))) * (acc[i][j]   - mean) * rstd;
            float o1 = (gv1 / (1.f + expf(-gv1))) * (acc[i][j+1] - mean) * rstd;
            hv[j>>1] = __floats2half2_rn(o0, o1);
        }
        *(uint2*)(rop + (size_t)r*E2_ + tc*8)     = *(uint2*)&hv[0];
        *(uint2*)(rop + (size_t)r*E2_ + tc*8 + 4) = *(uint2*)&hv[2];
    }
}

// ================= launch =================
extern "C" void kernel_launch(void* const* d_in, const int* in_sizes, int n_in,
                              void* d_out, int out_size)
{
    const float* x    = (const float*)d_in[0];
    const float* sn   = (const float*)d_in[1];
    const float* cs   = (const float*)d_in[2];
    const float* mask = (const float*)d_in[3];
    const float* cdec = (const float*)d_in[4];
    const float* idec = (const float*)d_in[5];
    const float* Wq = (const float*)d_in[6];
    const float* bq = (const float*)d_in[7];
    const float* Wk = (const float*)d_in[8];
    const float* bk = (const float*)d_in[9];
    const float* Wv = (const float*)d_in[10];
    const float* bv = (const float*)d_in[11];
    const float* Wg = (const float*)d_in[12];
    const float* bg = (const float*)d_in[13];
    const float* Wo = (const float*)d_in[14];
    const float* bo = (const float*)d_in[15];
    float* out = (float*)d_out;

    float *qp, *kp, *vp, *gp;
    __half *xh, *roh, *wqh, *wkh, *wvh, *wgh, *woh;
    cudaGetSymbolAddress((void**)&qp,  g_q);
    cudaGetSymbolAddress((void**)&kp,  g_k);
    cudaGetSymbolAddress((void**)&vp,  g_v);
    cudaGetSymbolAddress((void**)&gp,  g_gt);
    cudaGetSymbolAddress((void**)&xh,  g_xh);
    cudaGetSymbolAddress((void**)&roh, g_roh);
    cudaGetSymbolAddress((void**)&wqh, g_wqh);
    cudaGetSymbolAddress((void**)&wkh, g_wkh);
    cudaGetSymbolAddress((void**)&wvh, g_wvh);
    cudaGetSymbolAddress((void**)&wgh, g_wgh);
    cudaGetSymbolAddress((void**)&woh, g_woh);

    cudaFuncSetAttribute(gemm_h, cudaFuncAttributeMaxDynamicSharedMemorySize, GEMMH_SMEM);

    const int M = B_*T_;
    const float kscale = 1.0f / sqrtf((float)KD_);

    // f32 -> f16 staging
    f2h<<<(M*E_/4 + 255)/256, 256>>>(x, xh, M*E_/4);
    f2h<<<(E_*E_/4 + 255)/256, 256>>>(Wq, wqh, E_*E_/4);
    f2h<<<(E_*E_/4 + 255)/256, 256>>>(Wk, wkh, E_*E_/4);
    f2h<<<(E2_*E_/4 + 255)/256, 256>>>(Wv, wvh, E2_*E_/4);
    f2h<<<(E2_*E_/4 + 255)/256, 256>>>(Wg, wgh, E2_*E_/4);
    f2h<<<(E_*E2_/4 + 255)/256, 256>>>(Wo, woh, E_*E2_/4);

    gemm_h<<<dim3(E_/256,  M/128), 256, GEMMH_SMEM>>>(xh, wqh, bq, qp, E_,  E_,  1.f,    1, sn, cs);
    gemm_h<<<dim3(E_/256,  M/128), 256, GEMMH_SMEM>>>(xh, wkh, bk, kp, E_,  E_,  kscale, 1, sn, cs);
    gemm_h<<<dim3(E2_/256, M/128), 256, GEMMH_SMEM>>>(xh, wvh, bv, vp, E_,  E2_, 1.f,    0, sn, cs);
    gemm_h<<<dim3(E2_/256, M/128), 256, GEMMH_SMEM>>>(xh, wgh, bg, gp, E_,  E2_, 1.f,    0, sn, cs);
    qk_kernel   <<<2*NCHUNKS, 512>>>(mask);
    inner_kernel<<<2*NCHUNKS, 512>>>();
    kv_kernel   <<<NCHUNKS,   512>>>(mask);
    scan_kernel <<<B_*H_*(HD_/16), 256>>>(cdec);
    cross_kernel<<<2*NCHUNKS, 512>>>(idec);
    gemm_h<<<dim3(E_/256, M/128), 256, GEMMH_SMEM>>>(roh, woh, bo, out, E2_, E_, 1.f, 0, sn, cs);
}

// round 6
// speedup vs baseline: 1.1102x; 1.1102x over previous
#include <cuda_runtime.h>
#include <cuda_fp16.h>
#include <math.h>
#include <stdint.h>

#define B_ 2
#define T_ 4096
#define E_ 2048
#define E2_ 4096
#define H_ 16
#define KD_ 128
#define HD_ 256
#define CH_ 256
#define NC_ 16
#define NCHUNKS (B_*NC_*H_)   // 512

// ================= scratch =================
__device__ float g_q [B_*T_*E_];
__device__ float g_k [B_*T_*E_];
__device__ float g_v [B_*T_*E2_];
__device__ float g_gt[B_*T_*E2_];
__device__ float g_isc[NCHUNKS*CH_];
__device__ float g_inner[(size_t)NCHUNKS*CH_*HD_];
__device__ float g_kv [(size_t)NCHUNKS*KD_*HD_];
__device__ float g_kvr[(size_t)NCHUNKS*KD_*HD_];
__device__ float g_csc[NCHUNKS*HD_];
// half-precision staging
__device__ __half g_xh [B_*T_*E_];
__device__ __half g_roh[B_*T_*E2_];
__device__ __half g_wqh[E_*E_];
__device__ __half g_wkh[E_*E_];
__device__ __half g_wvh[(size_t)E2_*E_];
__device__ __half g_wgh[(size_t)E2_*E_];
__device__ __half g_woh[(size_t)E_*E2_];

// ================= helpers =================
__device__ __forceinline__ uint32_t smem_u32(const void* p) {
    uint32_t a;
    asm("{ .reg .u64 t; cvta.to.shared.u64 t, %1; cvt.u32.u64 %0, t; }" : "=r"(a) : "l"(p));
    return a;
}
__device__ __forceinline__ void cp16(uint32_t dst, const void* src) {
    asm volatile("cp.async.cg.shared.global [%0], [%1], 16;" :: "r"(dst), "l"(src));
}
__device__ __forceinline__ void cp_commit() { asm volatile("cp.async.commit_group;"); }
__device__ __forceinline__ void ldm_x4(uint32_t r[4], uint32_t addr) {
    asm volatile("ldmatrix.sync.aligned.m8n8.x4.shared.b16 {%0,%1,%2,%3}, [%4];"
        : "=r"(r[0]), "=r"(r[1]), "=r"(r[2]), "=r"(r[3]) : "r"(addr));
}
__device__ __forceinline__ void mma_f16(float c[4], const uint32_t a[4], const uint32_t b[2]) {
    asm volatile(
        "mma.sync.aligned.m16n8k16.row.col.f32.f16.f16.f32 "
        "{%0,%1,%2,%3}, {%4,%5,%6,%7}, {%8,%9}, {%0,%1,%2,%3};"
        : "+f"(c[0]), "+f"(c[1]), "+f"(c[2]), "+f"(c[3])
        : "r"(a[0]), "r"(a[1]), "r"(a[2]), "r"(a[3]), "r"(b[0]), "r"(b[1]));
}
// split one f32 pair into (hi,lo) half2 words
__device__ __forceinline__ void split2(float a, float b, uint32_t &hi, uint32_t &lo) {
    __half ha = __float2half_rn(a), hb = __float2half_rn(b);
    __half2 H = __halves2half2(ha, hb);
    hi = *reinterpret_cast<uint32_t*>(&H);
    __half2 L = __floats2half2_rn(a - __half2float(ha), b - __half2float(hb));
    lo = *reinterpret_cast<uint32_t*>(&L);
}
__device__ __forceinline__ void split8(const float4& u0, const float4& u1, uint4& hi, uint4& lo) {
    split2(u0.x, u0.y, hi.x, lo.x);
    split2(u0.z, u0.w, hi.y, lo.y);
    split2(u1.x, u1.y, hi.z, lo.z);
    split2(u1.z, u1.w, hi.w, lo.w);
}

// ================= f32 -> f16 converter =================
__global__ void f2h(const float* __restrict__ in, __half* __restrict__ out, int n4)
{
    int i = blockIdx.x * blockDim.x + threadIdx.x;
    if (i >= n4) return;
    float4 v = *(const float4*)(in + (size_t)i * 4);
    __half2 h[2];
    h[0] = __floats2half2_rn(v.x, v.y);
    h[1] = __floats2half2_rn(v.z, v.w);
    *(uint2*)(out + (size_t)i * 4) = *(uint2*)h;
}

// ===== fp16 tensor-core GEMM (R4 config): C = (A @ W^T + bias) * scale =====
#define BKH 64
#define PADH 72
#define TILEH (128*PADH*2)
#define GEMMH_SMEM (4*TILEH)

__global__ void __launch_bounds__(256)
gemm_h(const __half* __restrict__ A, const __half* __restrict__ W,
       const float* __restrict__ bias, float* __restrict__ C,
       int K, int Ncols, float scale)
{
    extern __shared__ __align__(128) char smh[];
    const int tid = threadIdx.x;
    const int wid = tid >> 5, lane = tid & 31;
    const int wm = wid & 1, wn = wid >> 1;
    const int g = lane >> 2, q = lane & 3;
    const int bx = blockIdx.x, by = blockIdx.y;

    const __half* Ab = A + (size_t)(by * 128) * K;
    const __half* Wb = W + (size_t)(bx * 128) * K;
    const uint32_t sb = smem_u32(smh);

    const int lr  = tid >> 1;
    const int lcu = (tid & 1) * 4;

    const int lrow8 = (lane & 7) + ((lane >> 3) & 1) * 8;
    const int koffB = (lane >> 4) * 16;

    float acc[4][4][4] = {};

    {
        const __half* As = Ab + (size_t)lr * K + lcu * 8;
        const __half* Ws = Wb + (size_t)lr * K + lcu * 8;
        uint32_t da = sb + (uint32_t)(lr * 144 + lcu * 16);
        uint32_t db = sb + 2u * TILEH + (uint32_t)(lr * 144 + lcu * 16);
        #pragma unroll
        for (int i = 0; i < 4; i++) { cp16(da + i * 16, As + i * 8); cp16(db + i * 16, Ws + i * 8); }
        cp_commit();
    }

    const int NS = K / BKH;
    for (int s = 0; s < NS; s++) {
        const int b = s & 1;
        if (s + 1 < NS) {
            const int nb = (s + 1) & 1;
            const __half* As = Ab + (size_t)lr * K + (s + 1) * BKH + lcu * 8;
            const __half* Ws = Wb + (size_t)lr * K + (s + 1) * BKH + lcu * 8;
            uint32_t da = sb + (uint32_t)nb * TILEH + (uint32_t)(lr * 144 + lcu * 16);
            uint32_t db = sb + (2u + nb) * TILEH + (uint32_t)(lr * 144 + lcu * 16);
            #pragma unroll
            for (int i = 0; i < 4; i++) { cp16(da + i * 16, As + i * 8); cp16(db + i * 16, Ws + i * 8); }
            cp_commit();
            asm volatile("cp.async.wait_group 1;");
        } else {
            asm volatile("cp.async.wait_group 0;");
        }
        __syncthreads();

        const uint32_t a_base = sb + (uint32_t)b * TILEH + (uint32_t)((wm * 64 + lrow8) * 144 + koffB);
        const uint32_t b_base = sb + 2u * TILEH + (uint32_t)b * TILEH + (uint32_t)((wn * 32 + lrow8) * 144 + koffB);
        #pragma unroll
        for (int ks = 0; ks < 4; ks++) {
            const uint32_t kc2 = ks * 32;
            uint32_t af[4][4];
            #pragma unroll
            for (int mf = 0; mf < 4; mf++) ldm_x4(af[mf], a_base + mf * 16 * 144 + kc2);
            uint32_t bf[4][2];
            #pragma unroll
            for (int nf2 = 0; nf2 < 2; nf2++) {
                uint32_t t4[4];
                ldm_x4(t4, b_base + nf2 * 16 * 144 + kc2);
                bf[2*nf2  ][0] = t4[0]; bf[2*nf2  ][1] = t4[2];
                bf[2*nf2+1][0] = t4[1]; bf[2*nf2+1][1] = t4[3];
            }
            #pragma unroll
            for (int mf = 0; mf < 4; mf++)
                #pragma unroll
                for (int nf = 0; nf < 4; nf++)
                    mma_f16(acc[mf][nf], af[mf], bf[nf]);
        }
        __syncthreads();
    }

    #pragma unroll
    for (int mf = 0; mf < 4; mf++) {
        #pragma unroll
        for (int nf = 0; nf < 4; nf++) {
            const int row = by * 128 + wm * 64 + mf * 16 + g;
            const int col = bx * 128 + wn * 32 + nf * 8 + q * 2;
            const float b0 = bias[col], b1 = bias[col + 1];
            float2 o0, o1;
            o0.x = (acc[mf][nf][0] + b0) * scale;
            o0.y = (acc[mf][nf][1] + b1) * scale;
            o1.x = (acc[mf][nf][2] + b0) * scale;
            o1.y = (acc[mf][nf][3] + b1) * scale;
            *(float2*)(C + (size_t)row * Ncols + col) = o0;
            *(float2*)(C + (size_t)(row + 8) * Ncols + col) = o1;
        }
    }
}

// ---------------- rotary (in-place on q and k) ----------------
__global__ void rotary_k(float* __restrict__ q, float* __restrict__ k,
                         const float* __restrict__ sn, const float* __restrict__ cs)
{
    int p = blockIdx.x * blockDim.x + threadIdx.x;
    if (p >= B_*T_*E_/2) return;
    int f = p * 2;
    int row = f / E_;
    int t = row % T_;
    int col = f % E_;
    int d = col % KD_;
    float2 qv = *(float2*)(q + (size_t)f);
    float2 kv = *(float2*)(k + (size_t)f);
    float c0 = cs[t*KD_ + d], c1 = cs[t*KD_ + d + 1];
    float s0 = sn[t*KD_ + d], s1 = sn[t*KD_ + d + 1];
    float2 qo, ko;
    qo.x = qv.x * c0 - qv.y * s0;
    qo.y = qv.y * c1 + qv.x * s1;
    ko.x = kv.x * c0 - kv.y * s0;
    ko.y = kv.y * c1 + kv.x * s1;
    *(float2*)(q + (size_t)f) = qo;
    *(float2*)(k + (size_t)f) = ko;
}

// ===== fused qk -> mask -> isc -> inner, split-fp16 tensor-core =====
// Block: 128 output rows x full chunk. 8 warps 2(M) x 4(N), warp tile 64x64.
#define P1   272                 // q/k tile row pitch bytes (128 halfs + 8 pad)
#define AQH_ 0
#define AQL_ 34816
#define BKHo 69632
#define BKLo 139264
#define PQ   528                 // qkm row pitch (256 halfs + 8 pad)
#define QKHo 0
#define QKLo 67584
#define PV   144                 // v^T slab row pitch (64 halfs + 8 pad)
#define VHo  135168
#define VLo  172032
#define ISCP 208896
#define ISCS 210944
#define QKI_SMEM 211456

__global__ void __launch_bounds__(256, 1)
qki_kernel(const float* __restrict__ mask)
{
    extern __shared__ __align__(128) char sm[];
    const uint32_t sb = smem_u32(sm);
    const int tid = threadIdx.x;
    const int wid = tid >> 5, lane = tid & 31;
    const int wm = wid & 1, wn = wid >> 1;
    const int g = lane >> 2, q = lane & 3;
    const int z = blockIdx.x, chunk = z >> 1, hf = z & 1;
    const int b = chunk / (NC_*H_);
    const int n = (chunk / H_) % NC_;
    const int h = chunk % H_;
    const int row0 = hf * 128;

    const int lrow8 = (lane & 7) + ((lane >> 3) & 1) * 8;
    const int koffB = (lane >> 4) * 16;

    // ---- stage q (128x128) and k (256x128) as split halves ----
    const float* qsrc = g_q + ((size_t)(b*T_ + n*CH_ + row0)) * E_ + h*KD_;
    const float* ksrc = g_k + ((size_t)(b*T_ + n*CH_)) * E_ + h*KD_;
    {
        const int r_ = tid >> 4, c_ = (tid & 15) * 8;
        #pragma unroll
        for (int p = 0; p < 8; p++) {
            int r = p * 16 + r_;
            float4 u0 = *(const float4*)(qsrc + (size_t)r * E_ + c_);
            float4 u1 = *(const float4*)(qsrc + (size_t)r * E_ + c_ + 4);
            uint4 hi, lo; split8(u0, u1, hi, lo);
            *(uint4*)(sm + AQH_ + r * P1 + c_ * 2) = hi;
            *(uint4*)(sm + AQL_ + r * P1 + c_ * 2) = lo;
        }
        #pragma unroll
        for (int p = 0; p < 16; p++) {
            int r = p * 16 + r_;
            float4 u0 = *(const float4*)(ksrc + (size_t)r * E_ + c_);
            float4 u1 = *(const float4*)(ksrc + (size_t)r * E_ + c_ + 4);
            uint4 hi, lo; split8(u0, u1, hi, lo);
            *(uint4*)(sm + BKHo + r * P1 + c_ * 2) = hi;
            *(uint4*)(sm + BKLo + r * P1 + c_ * 2) = lo;
        }
    }
    __syncthreads();

    float acc[4][8][4] = {};

    // ---- phase 1: qk = q @ k^T via 3 split passes ----
    {
        const uint32_t ao[3] = {AQH_, AQH_, AQL_};
        const uint32_t bo[3] = {BKHo, BKLo, BKHo};
        #pragma unroll
        for (int ps = 0; ps < 3; ps++) {
            const uint32_t a_base = sb + ao[ps] + (uint32_t)((wm*64 + lrow8) * P1 + koffB);
            const uint32_t b_base = sb + bo[ps] + (uint32_t)((wn*64 + lrow8) * P1 + koffB);
            #pragma unroll
            for (int ks = 0; ks < 8; ks++) {
                const uint32_t kb = ks * 32;
                uint32_t af[4][4];
                #pragma unroll
                for (int mf = 0; mf < 4; mf++) ldm_x4(af[mf], a_base + mf * 16 * P1 + kb);
                uint32_t bf[8][2];
                #pragma unroll
                for (int nf2 = 0; nf2 < 4; nf2++) {
                    uint32_t t4[4];
                    ldm_x4(t4, b_base + nf2 * 16 * P1 + kb);
                    bf[2*nf2  ][0] = t4[0]; bf[2*nf2  ][1] = t4[2];
                    bf[2*nf2+1][0] = t4[1]; bf[2*nf2+1][1] = t4[3];
                }
                #pragma unroll
                for (int mf = 0; mf < 4; mf++)
                    #pragma unroll
                    for (int nf = 0; nf < 8; nf++)
                        mma_f16(acc[mf][nf], af[mf], bf[nf]);
            }
        }
    }
    __syncthreads();   // all reads of q/k tiles done; regions reused below

    // ---- mask multiply, row |.| sums, split-store qkm into SMEM ----
    {
        float psl[4] = {0,0,0,0}, psh[4] = {0,0,0,0};
        const float* mbase = mask + (size_t)h * (CH_*CH_) + (size_t)row0 * CH_;
        #pragma unroll
        for (int mf = 0; mf < 4; mf++) {
            const int r0 = wm*64 + mf*16 + g, r1 = r0 + 8;
            const float* m0 = mbase + (size_t)r0 * CH_;
            const float* m1 = mbase + (size_t)r1 * CH_;
            #pragma unroll
            for (int nf = 0; nf < 8; nf++) {
                const int c0 = wn*64 + nf*8 + q*2;
                float v00 = acc[mf][nf][0] * m0[c0];
                float v01 = acc[mf][nf][1] * m0[c0+1];
                float v10 = acc[mf][nf][2] * m1[c0];
                float v11 = acc[mf][nf][3] * m1[c0+1];
                psl[mf] += fabsf(v00) + fabsf(v01);
                psh[mf] += fabsf(v10) + fabsf(v11);
                uint32_t h0, l0, h1, l1;
                split2(v00, v01, h0, l0);
                split2(v10, v11, h1, l1);
                *(uint32_t*)(sm + QKHo + r0 * PQ + c0 * 2) = h0;
                *(uint32_t*)(sm + QKLo + r0 * PQ + c0 * 2) = l0;
                *(uint32_t*)(sm + QKHo + r1 * PQ + c0 * 2) = h1;
                *(uint32_t*)(sm + QKLo + r1 * PQ + c0 * 2) = l1;
            }
        }
        float* iscp = (float*)(sm + ISCP);
        #pragma unroll
        for (int mf = 0; mf < 4; mf++) {
            float pl = psl[mf], ph = psh[mf];
            pl += __shfl_xor_sync(0xffffffffu, pl, 1);
            pl += __shfl_xor_sync(0xffffffffu, pl, 2);
            ph += __shfl_xor_sync(0xffffffffu, ph, 1);
            ph += __shfl_xor_sync(0xffffffffu, ph, 2);
            if (q == 0) {
                iscp[(wm*64 + mf*16 + g) * 4 + wn] = pl;
                iscp[(wm*64 + mf*16 + g + 8) * 4 + wn] = ph;
            }
        }
    }
    __syncthreads();
    if (tid < 128) {
        const float* ip = (const float*)(sm + ISCP) + tid * 4;
        float s = ip[0] + ip[1] + ip[2] + ip[3];
        g_isc[chunk*CH_ + row0 + tid] = s;
        ((float*)(sm + ISCS))[tid] = fmaxf(s, 1.f);
    }

    // ---- phase 2: inner = qkm @ v over 4 d-slabs of 64 ----
    #pragma unroll
    for (int mf = 0; mf < 4; mf++)
        #pragma unroll
        for (int nf = 0; nf < 8; nf++)
            #pragma unroll
            for (int e = 0; e < 4; e++) acc[mf][nf][e] = 0.f;

    const float* vsrc = g_v + ((size_t)(b*T_ + n*CH_)) * E2_ + h*HD_;
    for (int sl = 0; sl < 4; sl++) {
        __syncthreads();
        // stage v^T slab: global [d][v'] f32 -> SMEM [v'][d] split halves
        {
            const int d_ = tid >> 6;          // 0..3
            const int c_ = (tid & 63) * 4;    // v' base
            #pragma unroll
            for (int p = 0; p < 16; p++) {
                int dl = p * 4 + d_;
                int d = sl * 64 + dl;
                float4 u = *(const float4*)(vsrc + (size_t)d * E2_ + c_);
                float f[4] = {u.x, u.y, u.z, u.w};
                #pragma unroll
                for (int j = 0; j < 4; j++) {
                    __half hh = __float2half_rn(f[j]);
                    __half hl = __float2half_rn(f[j] - __half2float(hh));
                    *(uint16_t*)(sm + VHo + (c_ + j) * PV + dl * 2) = *(uint16_t*)&hh;
                    *(uint16_t*)(sm + VLo + (c_ + j) * PV + dl * 2) = *(uint16_t*)&hl;
                }
            }
        }
        __syncthreads();
        const uint32_t ao[3] = {QKHo, QKHo, QKLo};
        const uint32_t bo[3] = {VHo, VLo, VHo};
        #pragma unroll
        for (int ps = 0; ps < 3; ps++) {
            const uint32_t a_base = sb + ao[ps] + (uint32_t)((wm*64 + lrow8) * PQ + sl * 128 + koffB);
            const uint32_t b_base = sb + bo[ps] + (uint32_t)((wn*64 + lrow8) * PV + koffB);
            #pragma unroll
            for (int ks = 0; ks < 4; ks++) {
                const uint32_t kb = ks * 32;
                uint32_t af[4][4];
                #pragma unroll
                for (int mf = 0; mf < 4; mf++) ldm_x4(af[mf], a_base + mf * 16 * PQ + kb);
                uint32_t bf[8][2];
                #pragma unroll
                for (int nf2 = 0; nf2 < 4; nf2++) {
                    uint32_t t4[4];
                    ldm_x4(t4, b_base + nf2 * 16 * PV + kb);
                    bf[2*nf2  ][0] = t4[0]; bf[2*nf2  ][1] = t4[2];
                    bf[2*nf2+1][0] = t4[1]; bf[2*nf2+1][1] = t4[3];
                }
                #pragma unroll
                for (int mf = 0; mf < 4; mf++)
                    #pragma unroll
                    for (int nf = 0; nf < 8; nf++)
                        mma_f16(acc[mf][nf], af[mf], bf[nf]);
            }
        }
    }

    // ---- epilogue: scale rows by 1/clip(isc) and store inner ----
    {
        const float* iscs = (const float*)(sm + ISCS);
        float* op = g_inner + (size_t)chunk * (CH_*HD_) + (size_t)row0 * HD_;
        #pragma unroll
        for (int mf = 0; mf < 4; mf++) {
            const int r0 = wm*64 + mf*16 + g, r1 = r0 + 8;
            const float inv0 = 1.f / iscs[r0];
            const float inv1 = 1.f / iscs[r1];
            #pragma unroll
            for (int nf = 0; nf < 8; nf++) {
                const int c0 = wn*64 + nf*8 + q*2;
                float2 o0, o1;
                o0.x = acc[mf][nf][0] * inv0;
                o0.y = acc[mf][nf][1] * inv0;
                o1.x = acc[mf][nf][2] * inv1;
                o1.y = acc[mf][nf][3] * inv1;
                *(float2*)(op + (size_t)r0 * HD_ + c0) = o0;
                *(float2*)(op + (size_t)r1 * HD_ + c0) = o1;
            }
        }
    }
}

// ================= fp32 8x8 microkernel step =================
__device__ __forceinline__ void mk_step(const float* a, const float* b, float acc[8][8]) {
    float rm[8], rn[8];
    *(float4*)&rm[0] = *(const float4*)(a);
    *(float4*)&rm[4] = *(const float4*)(a + 4);
    *(float4*)&rn[0] = *(const float4*)(b);
    *(float4*)&rn[4] = *(const float4*)(b + 4);
    #pragma unroll
    for (int i = 0; i < 8; i++)
        #pragma unroll
        for (int j = 0; j < 8; j++)
            acc[i][j] += rm[i] * rn[j];
}

// ---------------- kv[k,v] = sum_c kr[c,k]*maskrow[c]*vc[c,v] ----------------
__global__ __launch_bounds__(512)
void kv_kernel(const float* __restrict__ mask)
{
    __shared__ float As[8][128];
    __shared__ float Bs[8][256];
    const int chunk = blockIdx.x;
    const int b = chunk / (NC_*H_);
    const int n = (chunk / H_) % NC_;
    const int h = chunk % H_;
    const int tid = threadIdx.x;
    const int tr = tid >> 5, tc = tid & 31;
    const float* Kb = g_k + ((size_t)(b*T_ + n*CH_)) * E_ + h*KD_;
    const float* Vb = g_v + ((size_t)(b*T_ + n*CH_)) * E2_ + h*HD_;
    const float* wrow = mask + (size_t)h * (CH_*CH_) + (size_t)(CH_-1) * CH_;
    const int acc_cc = tid >> 6;
    const int a_kcol = (tid & 63) * 2;
    const int b_vcol = (tid & 63) * 4;
    float acc[8][8] = {};
    for (int c0 = 0; c0 < CH_; c0 += 8) {
        float w = wrow[c0 + acc_cc];
        float2 a2 = *(const float2*)(Kb + (size_t)(c0 + acc_cc) * E_ + a_kcol);
        As[acc_cc][a_kcol  ] = a2.x * w;
        As[acc_cc][a_kcol+1] = a2.y * w;
        float4 b4 = *(const float4*)(Vb + (size_t)(c0 + acc_cc) * E2_ + b_vcol);
        *(float4*)&Bs[acc_cc][b_vcol] = b4;
        __syncthreads();
        #pragma unroll
        for (int kk = 0; kk < 8; kk++) mk_step(&As[kk][tr*8], &Bs[kk][tc*8], acc);
        __syncthreads();
    }
    float* op = g_kv + (size_t)chunk * (KD_*HD_);
    #pragma unroll
    for (int i = 0; i < 8; i++)
        #pragma unroll
        for (int j = 0; j < 8; j++)
            op[(size_t)(tr*8+i)*HD_ + tc*8 + j] = acc[i][j];
}

// ---------------- cross-chunk scan ----------------
__global__ __launch_bounds__(256)
void scan_kernel(const float* __restrict__ cdec)
{
    const int vb = blockIdx.x & 15;
    const int bh = blockIdx.x >> 4;
    const int b = bh / H_, h = bh % H_;
    const int v0 = vb * 16;
    const int tid = threadIdx.x;
    const int v = tid & 15;
    const int kg = tid >> 4;
    float s[8] = {0,0,0,0,0,0,0,0};
    __shared__ float sc[16];
    __shared__ float red[256];
    if (tid < 16) sc[tid] = 1.f;
    __syncthreads();
    const float cd = cdec[h];
    for (int n = 0; n < NC_; n++) {
        const int chunk = (b*NC_ + n)*H_ + h;
        const size_t zo = (size_t)chunk * (KD_*HD_);
        float invsc = 1.f / sc[v];
        #pragma unroll
        for (int i = 0; i < 8; i++)
            g_kvr[zo + (size_t)(kg*8+i)*HD_ + v0 + v] = s[i] * invsc;
        if (tid < 16) g_csc[chunk*HD_ + v0 + tid] = sc[tid];
        float p = 0.f;
        #pragma unroll
        for (int i = 0; i < 8; i++) {
            s[i] = s[i]*cd + g_kv[zo + (size_t)(kg*8+i)*HD_ + v0 + v];
            p += fabsf(s[i]);
        }
        red[tid] = p;
        __syncthreads();
        if (tid < 16) {
            float sum = 0.f;
            #pragma unroll
            for (int j = 0; j < 16; j++) sum += red[j*16 + tid];
            sc[tid] = fmaxf(sum, 1.f);
        }
        __syncthreads();
    }
}

// ------- cross = (qr*idec) @ kv_rec; combine + LN + silu(g) gate -> half -------
__global__ __launch_bounds__(512)
void cross_kernel(const float* __restrict__ idec)
{
    __shared__ float As[8][128];
    __shared__ float Bs[8][256];
    const int z = blockIdx.x;
    const int chunk = z >> 1, hf = z & 1;
    const int b = chunk / (NC_*H_);
    const int n = (chunk / H_) % NC_;
    const int h = chunk % H_;
    const int row0 = hf * 128;
    const int tid = threadIdx.x;
    const int tr = tid >> 5, tc = tid & 31;
    const float* Ab = g_q + ((size_t)(b*T_ + n*CH_ + row0)) * E_ + h*KD_;
    const float* Bb = g_kvr + (size_t)chunk * (KD_*HD_);
    const int a_row = tid >> 2, a_k = (tid & 3) * 2;
    const int bkk = tid >> 6, bv = (tid & 63) * 4;
    const float aw = idec[h*CH_ + row0 + a_row];
    float acc[8][8] = {};
    for (int k0 = 0; k0 < KD_; k0 += 8) {
        float2 a2 = *(const float2*)(Ab + (size_t)a_row * E_ + k0 + a_k);
        As[a_k  ][a_row] = a2.x * aw;
        As[a_k+1][a_row] = a2.y * aw;
        float4 b4 = *(const float4*)(Bb + (size_t)(k0 + bkk) * HD_ + bv);
        *(float4*)&Bs[bkk][bv] = b4;
        __syncthreads();
        #pragma unroll
        for (int kk = 0; kk < 8; kk++) mk_step(&As[kk][tr*8], &Bs[kk][tc*8], acc);
        __syncthreads();
    }
    const float* innp = g_inner + (size_t)chunk * (CH_*HD_) + (size_t)row0 * HD_;
    const float* cscp = g_csc + chunk*HD_;
    const float* gp   = g_gt + ((size_t)(b*T_ + n*CH_ + row0)) * E2_ + h*HD_;
    __half* rop       = g_roh + ((size_t)(b*T_ + n*CH_ + row0)) * E2_ + h*HD_;
    #pragma unroll
    for (int i = 0; i < 8; i++) {
        int r = tr*8 + i;
        float isc = fmaxf(g_isc[chunk*CH_ + row0 + r], 1.f);
        float rsum = 0.f, rsq = 0.f;
        #pragma unroll
        for (int j = 0; j < 8; j++) {
            int c = tc*8 + j;
            float o = innp[(size_t)r*HD_ + c] / cscp[c] + acc[i][j] / isc;
            acc[i][j] = o;
            rsum += o;
            rsq  += o*o;
        }
        #pragma unroll
        for (int off = 16; off > 0; off >>= 1) {
            rsum += __shfl_xor_sync(0xffffffffu, rsum, off);
            rsq  += __shfl_xor_sync(0xffffffffu, rsq,  off);
        }
        float mean = rsum * (1.f/HD_);
        float var  = rsq  * (1.f/HD_) - mean*mean;
        float rstd = rsqrtf(var + 1e-5f);
        __half2 hv[4];
        #pragma unroll
        for (int j = 0; j < 8; j += 2) {
            int c = tc*8 + j;
            float gv0 = gp[(size_t)r*E2_ + c];
            float gv1 = gp[(size_t)r*E2_ + c + 1];
            float o0 = (gv0 / (1.f + expf(-gv0))) * (acc[i][j]   - mean) * rstd;
            float o1 = (gv1 / (1.f + expf(-gv1))) * (acc[i][j+1] - mean) * rstd;
            hv[j>>1] = __floats2half2_rn(o0, o1);
        }
        *(uint2*)(rop + (size_t)r*E2_ + tc*8)     = *(uint2*)&hv[0];
        *(uint2*)(rop + (size_t)r*E2_ + tc*8 + 4) = *(uint2*)&hv[2];
    }
}

// ================= launch =================
extern "C" void kernel_launch(void* const* d_in, const int* in_sizes, int n_in,
                              void* d_out, int out_size)
{
    const float* x    = (const float*)d_in[0];
    const float* sn   = (const float*)d_in[1];
    const float* cs   = (const float*)d_in[2];
    const float* mask = (const float*)d_in[3];
    const float* cdec = (const float*)d_in[4];
    const float* idec = (const float*)d_in[5];
    const float* Wq = (const float*)d_in[6];
    const float* bq = (const float*)d_in[7];
    const float* Wk = (const float*)d_in[8];
    const float* bk = (const float*)d_in[9];
    const float* Wv = (const float*)d_in[10];
    const float* bv = (const float*)d_in[11];
    const float* Wg = (const float*)d_in[12];
    const float* bg = (const float*)d_in[13];
    const float* Wo = (const float*)d_in[14];
    const float* bo = (const float*)d_in[15];
    float* out = (float*)d_out;

    float *qp, *kp, *vp, *gp;
    __half *xh, *roh, *wqh, *wkh, *wvh, *wgh, *woh;
    cudaGetSymbolAddress((void**)&qp,  g_q);
    cudaGetSymbolAddress((void**)&kp,  g_k);
    cudaGetSymbolAddress((void**)&vp,  g_v);
    cudaGetSymbolAddress((void**)&gp,  g_gt);
    cudaGetSymbolAddress((void**)&xh,  g_xh);
    cudaGetSymbolAddress((void**)&roh, g_roh);
    cudaGetSymbolAddress((void**)&wqh, g_wqh);
    cudaGetSymbolAddress((void**)&wkh, g_wkh);
    cudaGetSymbolAddress((void**)&wvh, g_wvh);
    cudaGetSymbolAddress((void**)&wgh, g_wgh);
    cudaGetSymbolAddress((void**)&woh, g_woh);

    cudaFuncSetAttribute(gemm_h, cudaFuncAttributeMaxDynamicSharedMemorySize, GEMMH_SMEM);
    cudaFuncSetAttribute(qki_kernel, cudaFuncAttributeMaxDynamicSharedMemorySize, QKI_SMEM);

    const int M = B_*T_;
    const float kscale = 1.0f / sqrtf((float)KD_);

    f2h<<<(M*E_/4 + 255)/256, 256>>>(x, xh, M*E_/4);
    f2h<<<(E_*E_/4 + 255)/256, 256>>>(Wq, wqh, E_*E_/4);
    f2h<<<(E_*E_/4 + 255)/256, 256>>>(Wk, wkh, E_*E_/4);
    f2h<<<(E2_*E_/4 + 255)/256, 256>>>(Wv, wvh, E2_*E_/4);
    f2h<<<(E2_*E_/4 + 255)/256, 256>>>(Wg, wgh, E2_*E_/4);
    f2h<<<(E_*E2_/4 + 255)/256, 256>>>(Wo, woh, E_*E2_/4);

    gemm_h<<<dim3(E_/128,  M/128), 256, GEMMH_SMEM>>>(xh, wqh, bq, qp, E_,  E_,  1.f);
    gemm_h<<<dim3(E_/128,  M/128), 256, GEMMH_SMEM>>>(xh, wkh, bk, kp, E_,  E_,  kscale);
    gemm_h<<<dim3(E2_/128, M/128), 256, GEMMH_SMEM>>>(xh, wvh, bv, vp, E_,  E2_, 1.f);
    gemm_h<<<dim3(E2_/128, M/128), 256, GEMMH_SMEM>>>(xh, wgh, bg, gp, E_,  E2_, 1.f);
    rotary_k<<<(B_*T_*E_/2 + 255)/256, 256>>>(qp, kp, sn, cs);
    qki_kernel  <<<2*NCHUNKS, 256, QKI_SMEM>>>(mask);
    kv_kernel   <<<NCHUNKS,   512>>>(mask);
    scan_kernel <<<B_*H_*(HD_/16), 256>>>(cdec);
    cross_kernel<<<2*NCHUNKS, 512>>>(idec);
    gemm_h<<<dim3(E_/128, M/128), 256, GEMMH_SMEM>>>(roh, woh, bo, out, E2_, E_, 1.f);
}

// round 7
// speedup vs baseline: 1.1375x; 1.0246x over previous
#include <cuda_runtime.h>
#include <cuda_fp16.h>
#include <math.h>
#include <stdint.h>

#define B_ 2
#define T_ 4096
#define E_ 2048
#define E2_ 4096
#define H_ 16
#define KD_ 128
#define HD_ 256
#define CH_ 256
#define NC_ 16
#define NCHUNKS (B_*NC_*H_)   // 512

// ================= scratch =================
__device__ float g_q [B_*T_*E_];
__device__ float g_k [B_*T_*E_];
__device__ float g_v [B_*T_*E2_];
__device__ float g_gt[B_*T_*E2_];
__device__ float g_isc[NCHUNKS*CH_];
__device__ float g_inner[(size_t)NCHUNKS*CH_*HD_];
__device__ float g_kv [(size_t)NCHUNKS*KD_*HD_];
__device__ float g_kvr[(size_t)NCHUNKS*KD_*HD_];
__device__ float g_csc[NCHUNKS*HD_];
__device__ __half g_xh [B_*T_*E_];
__device__ __half g_roh[B_*T_*E2_];
__device__ __half g_wqh[E_*E_];
__device__ __half g_wkh[E_*E_];
__device__ __half g_wvh[(size_t)E2_*E_];
__device__ __half g_wgh[(size_t)E2_*E_];
__device__ __half g_woh[(size_t)E_*E2_];

// ================= helpers =================
__device__ __forceinline__ uint32_t smem_u32(const void* p) {
    uint32_t a;
    asm("{ .reg .u64 t; cvta.to.shared.u64 t, %1; cvt.u32.u64 %0, t; }" : "=r"(a) : "l"(p));
    return a;
}
__device__ __forceinline__ void cp16(uint32_t dst, const void* src) {
    asm volatile("cp.async.cg.shared.global [%0], [%1], 16;" :: "r"(dst), "l"(src));
}
__device__ __forceinline__ void cp_commit() { asm volatile("cp.async.commit_group;"); }
__device__ __forceinline__ void ldm_x4(uint32_t r[4], uint32_t addr) {
    asm volatile("ldmatrix.sync.aligned.m8n8.x4.shared.b16 {%0,%1,%2,%3}, [%4];"
        : "=r"(r[0]), "=r"(r[1]), "=r"(r[2]), "=r"(r[3]) : "r"(addr));
}
__device__ __forceinline__ void mma_f16(float c[4], const uint32_t a[4], const uint32_t b[2]) {
    asm volatile(
        "mma.sync.aligned.m16n8k16.row.col.f32.f16.f16.f32 "
        "{%0,%1,%2,%3}, {%4,%5,%6,%7}, {%8,%9}, {%0,%1,%2,%3};"
        : "+f"(c[0]), "+f"(c[1]), "+f"(c[2]), "+f"(c[3])
        : "r"(a[0]), "r"(a[1]), "r"(a[2]), "r"(a[3]), "r"(b[0]), "r"(b[1]));
}
__device__ __forceinline__ void split2(float a, float b, uint32_t &hi, uint32_t &lo) {
    __half ha = __float2half_rn(a), hb = __float2half_rn(b);
    __half2 H = __halves2half2(ha, hb);
    hi = *reinterpret_cast<uint32_t*>(&H);
    __half2 L = __floats2half2_rn(a - __half2float(ha), b - __half2float(hb));
    lo = *reinterpret_cast<uint32_t*>(&L);
}
__device__ __forceinline__ void split8(const float4& u0, const float4& u1, uint4& hi, uint4& lo) {
    split2(u0.x, u0.y, hi.x, lo.x);
    split2(u0.z, u0.w, hi.y, lo.y);
    split2(u1.x, u1.y, hi.z, lo.z);
    split2(u1.z, u1.w, hi.w, lo.w);
}
__device__ __forceinline__ void split_store16(char* base_h, char* base_l, int row, int pitch, int col, float f) {
    __half hh = __float2half_rn(f);
    __half hl = __float2half_rn(f - __half2float(hh));
    *(uint16_t*)(base_h + row * pitch + col * 2) = *(uint16_t*)&hh;
    *(uint16_t*)(base_l + row * pitch + col * 2) = *(uint16_t*)&hl;
}

// ================= f32 -> f16 converter =================
__global__ void f2h(const float* __restrict__ in, __half* __restrict__ out, int n4)
{
    int i = blockIdx.x * blockDim.x + threadIdx.x;
    if (i >= n4) return;
    float4 v = *(const float4*)(in + (size_t)i * 4);
    __half2 h[2];
    h[0] = __floats2half2_rn(v.x, v.y);
    h[1] = __floats2half2_rn(v.z, v.w);
    *(uint2*)(out + (size_t)i * 4) = *(uint2*)h;
}

// ===== fp16 tensor-core GEMM (R4 config): C = (A @ W^T + bias) * scale =====
#define BKH 64
#define PADH 72
#define TILEH (128*PADH*2)
#define GEMMH_SMEM (4*TILEH)

__global__ void __launch_bounds__(256)
gemm_h(const __half* __restrict__ A, const __half* __restrict__ W,
       const float* __restrict__ bias, float* __restrict__ C,
       int K, int Ncols, float scale)
{
    extern __shared__ __align__(128) char smh[];
    const int tid = threadIdx.x;
    const int wid = tid >> 5, lane = tid & 31;
    const int wm = wid & 1, wn = wid >> 1;
    const int g = lane >> 2, q = lane & 3;
    const int bx = blockIdx.x, by = blockIdx.y;

    const __half* Ab = A + (size_t)(by * 128) * K;
    const __half* Wb = W + (size_t)(bx * 128) * K;
    const uint32_t sb = smem_u32(smh);

    const int lr  = tid >> 1;
    const int lcu = (tid & 1) * 4;
    const int lrow8 = (lane & 7) + ((lane >> 3) & 1) * 8;
    const int koffB = (lane >> 4) * 16;

    float acc[4][4][4] = {};

    {
        const __half* As = Ab + (size_t)lr * K + lcu * 8;
        const __half* Ws = Wb + (size_t)lr * K + lcu * 8;
        uint32_t da = sb + (uint32_t)(lr * 144 + lcu * 16);
        uint32_t db = sb + 2u * TILEH + (uint32_t)(lr * 144 + lcu * 16);
        #pragma unroll
        for (int i = 0; i < 4; i++) { cp16(da + i * 16, As + i * 8); cp16(db + i * 16, Ws + i * 8); }
        cp_commit();
    }

    const int NS = K / BKH;
    for (int s = 0; s < NS; s++) {
        const int b = s & 1;
        if (s + 1 < NS) {
            const int nb = (s + 1) & 1;
            const __half* As = Ab + (size_t)lr * K + (s + 1) * BKH + lcu * 8;
            const __half* Ws = Wb + (size_t)lr * K + (s + 1) * BKH + lcu * 8;
            uint32_t da = sb + (uint32_t)nb * TILEH + (uint32_t)(lr * 144 + lcu * 16);
            uint32_t db = sb + (2u + nb) * TILEH + (uint32_t)(lr * 144 + lcu * 16);
            #pragma unroll
            for (int i = 0; i < 4; i++) { cp16(da + i * 16, As + i * 8); cp16(db + i * 16, Ws + i * 8); }
            cp_commit();
            asm volatile("cp.async.wait_group 1;");
        } else {
            asm volatile("cp.async.wait_group 0;");
        }
        __syncthreads();

        const uint32_t a_base = sb + (uint32_t)b * TILEH + (uint32_t)((wm * 64 + lrow8) * 144 + koffB);
        const uint32_t b_base = sb + 2u * TILEH + (uint32_t)b * TILEH + (uint32_t)((wn * 32 + lrow8) * 144 + koffB);
        #pragma unroll
        for (int ks = 0; ks < 4; ks++) {
            const uint32_t kc2 = ks * 32;
            uint32_t af[4][4];
            #pragma unroll
            for (int mf = 0; mf < 4; mf++) ldm_x4(af[mf], a_base + mf * 16 * 144 + kc2);
            uint32_t bf[4][2];
            #pragma unroll
            for (int nf2 = 0; nf2 < 2; nf2++) {
                uint32_t t4[4];
                ldm_x4(t4, b_base + nf2 * 16 * 144 + kc2);
                bf[2*nf2  ][0] = t4[0]; bf[2*nf2  ][1] = t4[2];
                bf[2*nf2+1][0] = t4[1]; bf[2*nf2+1][1] = t4[3];
            }
            #pragma unroll
            for (int mf = 0; mf < 4; mf++)
                #pragma unroll
                for (int nf = 0; nf < 4; nf++)
                    mma_f16(acc[mf][nf], af[mf], bf[nf]);
        }
        __syncthreads();
    }

    #pragma unroll
    for (int mf = 0; mf < 4; mf++) {
        #pragma unroll
        for (int nf = 0; nf < 4; nf++) {
            const int row = by * 128 + wm * 64 + mf * 16 + g;
            const int col = bx * 128 + wn * 32 + nf * 8 + q * 2;
            const float b0 = bias[col], b1 = bias[col + 1];
            float2 o0, o1;
            o0.x = (acc[mf][nf][0] + b0) * scale;
            o0.y = (acc[mf][nf][1] + b1) * scale;
            o1.x = (acc[mf][nf][2] + b0) * scale;
            o1.y = (acc[mf][nf][3] + b1) * scale;
            *(float2*)(C + (size_t)row * Ncols + col) = o0;
            *(float2*)(C + (size_t)(row + 8) * Ncols + col) = o1;
        }
    }
}

// ---------------- rotary (in-place on q and k) ----------------
__global__ void rotary_k(float* __restrict__ q, float* __restrict__ k,
                         const float* __restrict__ sn, const float* __restrict__ cs)
{
    int p = blockIdx.x * blockDim.x + threadIdx.x;
    if (p >= B_*T_*E_/2) return;
    int f = p * 2;
    int row = f / E_;
    int t = row % T_;
    int col = f % E_;
    int d = col % KD_;
    float2 qv = *(float2*)(q + (size_t)f);
    float2 kv = *(float2*)(k + (size_t)f);
    float c0 = cs[t*KD_ + d], c1 = cs[t*KD_ + d + 1];
    float s0 = sn[t*KD_ + d], s1 = sn[t*KD_ + d + 1];
    float2 qo, ko;
    qo.x = qv.x * c0 - qv.y * s0;
    qo.y = qv.y * c1 + qv.x * s1;
    ko.x = kv.x * c0 - kv.y * s0;
    ko.y = kv.y * c1 + kv.x * s1;
    *(float2*)(q + (size_t)f) = qo;
    *(float2*)(k + (size_t)f) = ko;
}

// ===== fused qk -> mask -> isc -> inner (split-fp16) =====
#define P1   272
#define AQH_ 0
#define AQL_ 34816
#define BKHo 69632
#define BKLo 139264
#define PQ   528
#define QKHo 0
#define QKLo 67584
#define PV   144
#define VHo  135168
#define VLo  172032
#define ISCP 208896
#define ISCS 210944
#define QKI_SMEM 211456

__global__ void __launch_bounds__(256, 1)
qki_kernel(const float* __restrict__ mask)
{
    extern __shared__ __align__(128) char sm[];
    const uint32_t sb = smem_u32(sm);
    const int tid = threadIdx.x;
    const int wid = tid >> 5, lane = tid & 31;
    const int wm = wid & 1, wn = wid >> 1;
    const int g = lane >> 2, q = lane & 3;
    const int z = blockIdx.x, chunk = z >> 1, hf = z & 1;
    const int b = chunk / (NC_*H_);
    const int n = (chunk / H_) % NC_;
    const int h = chunk % H_;
    const int row0 = hf * 128;

    const int lrow8 = (lane & 7) + ((lane >> 3) & 1) * 8;
    const int koffB = (lane >> 4) * 16;

    const float* qsrc = g_q + ((size_t)(b*T_ + n*CH_ + row0)) * E_ + h*KD_;
    const float* ksrc = g_k + ((size_t)(b*T_ + n*CH_)) * E_ + h*KD_;
    {
        const int r_ = tid >> 4, c_ = (tid & 15) * 8;
        #pragma unroll
        for (int p = 0; p < 8; p++) {
            int r = p * 16 + r_;
            float4 u0 = *(const float4*)(qsrc + (size_t)r * E_ + c_);
            float4 u1 = *(const float4*)(qsrc + (size_t)r * E_ + c_ + 4);
            uint4 hi, lo; split8(u0, u1, hi, lo);
            *(uint4*)(sm + AQH_ + r * P1 + c_ * 2) = hi;
            *(uint4*)(sm + AQL_ + r * P1 + c_ * 2) = lo;
        }
        #pragma unroll
        for (int p = 0; p < 16; p++) {
            int r = p * 16 + r_;
            float4 u0 = *(const float4*)(ksrc + (size_t)r * E_ + c_);
            float4 u1 = *(const float4*)(ksrc + (size_t)r * E_ + c_ + 4);
            uint4 hi, lo; split8(u0, u1, hi, lo);
            *(uint4*)(sm + BKHo + r * P1 + c_ * 2) = hi;
            *(uint4*)(sm + BKLo + r * P1 + c_ * 2) = lo;
        }
    }
    __syncthreads();

    float acc[4][8][4] = {};

    {
        const uint32_t ao[3] = {AQH_, AQH_, AQL_};
        const uint32_t bo[3] = {BKHo, BKLo, BKHo};
        #pragma unroll
        for (int ps = 0; ps < 3; ps++) {
            const uint32_t a_base = sb + ao[ps] + (uint32_t)((wm*64 + lrow8) * P1 + koffB);
            const uint32_t b_base = sb + bo[ps] + (uint32_t)((wn*64 + lrow8) * P1 + koffB);
            #pragma unroll
            for (int ks = 0; ks < 8; ks++) {
                const uint32_t kb = ks * 32;
                uint32_t af[4][4];
                #pragma unroll
                for (int mf = 0; mf < 4; mf++) ldm_x4(af[mf], a_base + mf * 16 * P1 + kb);
                uint32_t bf[8][2];
                #pragma unroll
                for (int nf2 = 0; nf2 < 4; nf2++) {
                    uint32_t t4[4];
                    ldm_x4(t4, b_base + nf2 * 16 * P1 + kb);
                    bf[2*nf2  ][0] = t4[0]; bf[2*nf2  ][1] = t4[2];
                    bf[2*nf2+1][0] = t4[1]; bf[2*nf2+1][1] = t4[3];
                }
                #pragma unroll
                for (int mf = 0; mf < 4; mf++)
                    #pragma unroll
                    for (int nf = 0; nf < 8; nf++)
                        mma_f16(acc[mf][nf], af[mf], bf[nf]);
            }
        }
    }
    __syncthreads();

    {
        float psl[4] = {0,0,0,0}, psh[4] = {0,0,0,0};
        const float* mbase = mask + (size_t)h * (CH_*CH_) + (size_t)row0 * CH_;
        #pragma unroll
        for (int mf = 0; mf < 4; mf++) {
            const int r0 = wm*64 + mf*16 + g, r1 = r0 + 8;
            const float* m0 = mbase + (size_t)r0 * CH_;
            const float* m1 = mbase + (size_t)r1 * CH_;
            #pragma unroll
            for (int nf = 0; nf < 8; nf++) {
                const int c0 = wn*64 + nf*8 + q*2;
                float v00 = acc[mf][nf][0] * m0[c0];
                float v01 = acc[mf][nf][1] * m0[c0+1];
                float v10 = acc[mf][nf][2] * m1[c0];
                float v11 = acc[mf][nf][3] * m1[c0+1];
                psl[mf] += fabsf(v00) + fabsf(v01);
                psh[mf] += fabsf(v10) + fabsf(v11);
                uint32_t h0, l0, h1, l1;
                split2(v00, v01, h0, l0);
                split2(v10, v11, h1, l1);
                *(uint32_t*)(sm + QKHo + r0 * PQ + c0 * 2) = h0;
                *(uint32_t*)(sm + QKLo + r0 * PQ + c0 * 2) = l0;
                *(uint32_t*)(sm + QKHo + r1 * PQ + c0 * 2) = h1;
                *(uint32_t*)(sm + QKLo + r1 * PQ + c0 * 2) = l1;
            }
        }
        float* iscp = (float*)(sm + ISCP);
        #pragma unroll
        for (int mf = 0; mf < 4; mf++) {
            float pl = psl[mf], ph = psh[mf];
            pl += __shfl_xor_sync(0xffffffffu, pl, 1);
            pl += __shfl_xor_sync(0xffffffffu, pl, 2);
            ph += __shfl_xor_sync(0xffffffffu, ph, 1);
            ph += __shfl_xor_sync(0xffffffffu, ph, 2);
            if (q == 0) {
                iscp[(wm*64 + mf*16 + g) * 4 + wn] = pl;
                iscp[(wm*64 + mf*16 + g + 8) * 4 + wn] = ph;
            }
        }
    }
    __syncthreads();
    if (tid < 128) {
        const float* ip = (const float*)(sm + ISCP) + tid * 4;
        float s = ip[0] + ip[1] + ip[2] + ip[3];
        g_isc[chunk*CH_ + row0 + tid] = s;
        ((float*)(sm + ISCS))[tid] = fmaxf(s, 1.f);
    }

    #pragma unroll
    for (int mf = 0; mf < 4; mf++)
        #pragma unroll
        for (int nf = 0; nf < 8; nf++)
            #pragma unroll
            for (int e = 0; e < 4; e++) acc[mf][nf][e] = 0.f;

    const float* vsrc = g_v + ((size_t)(b*T_ + n*CH_)) * E2_ + h*HD_;
    for (int sl = 0; sl < 4; sl++) {
        __syncthreads();
        {
            const int d_ = tid >> 6;
            const int c_ = (tid & 63) * 4;
            #pragma unroll
            for (int p = 0; p < 16; p++) {
                int dl = p * 4 + d_;
                int d = sl * 64 + dl;
                float4 u = *(const float4*)(vsrc + (size_t)d * E2_ + c_);
                const float f[4] = {u.x, u.y, u.z, u.w};
                #pragma unroll
                for (int j = 0; j < 4; j++)
                    split_store16(sm + VHo, sm + VLo, c_ + j, PV, dl, f[j]);
            }
        }
        __syncthreads();
        const uint32_t ao[3] = {QKHo, QKHo, QKLo};
        const uint32_t bo[3] = {VHo, VLo, VHo};
        #pragma unroll
        for (int ps = 0; ps < 3; ps++) {
            const uint32_t a_base = sb + ao[ps] + (uint32_t)((wm*64 + lrow8) * PQ + sl * 128 + koffB);
            const uint32_t b_base = sb + bo[ps] + (uint32_t)((wn*64 + lrow8) * PV + koffB);
            #pragma unroll
            for (int ks = 0; ks < 4; ks++) {
                const uint32_t kb = ks * 32;
                uint32_t af[4][4];
                #pragma unroll
                for (int mf = 0; mf < 4; mf++) ldm_x4(af[mf], a_base + mf * 16 * PQ + kb);
                uint32_t bf[8][2];
                #pragma unroll
                for (int nf2 = 0; nf2 < 4; nf2++) {
                    uint32_t t4[4];
                    ldm_x4(t4, b_base + nf2 * 16 * PV + kb);
                    bf[2*nf2  ][0] = t4[0]; bf[2*nf2  ][1] = t4[2];
                    bf[2*nf2+1][0] = t4[1]; bf[2*nf2+1][1] = t4[3];
                }
                #pragma unroll
                for (int mf = 0; mf < 4; mf++)
                    #pragma unroll
                    for (int nf = 0; nf < 8; nf++)
                        mma_f16(acc[mf][nf], af[mf], bf[nf]);
            }
        }
    }

    {
        const float* iscs = (const float*)(sm + ISCS);
        float* op = g_inner + (size_t)chunk * (CH_*HD_) + (size_t)row0 * HD_;
        #pragma unroll
        for (int mf = 0; mf < 4; mf++) {
            const int r0 = wm*64 + mf*16 + g, r1 = r0 + 8;
            const float inv0 = 1.f / iscs[r0];
            const float inv1 = 1.f / iscs[r1];
            #pragma unroll
            for (int nf = 0; nf < 8; nf++) {
                const int c0 = wn*64 + nf*8 + q*2;
                float2 o0, o1;
                o0.x = acc[mf][nf][0] * inv0;
                o0.y = acc[mf][nf][1] * inv0;
                o1.x = acc[mf][nf][2] * inv1;
                o1.y = acc[mf][nf][3] * inv1;
                *(float2*)(op + (size_t)r0 * HD_ + c0) = o0;
                *(float2*)(op + (size_t)r1 * HD_ + c0) = o1;
            }
        }
    }
}

// ===== kv = (w*k)^T @ v  (split-fp16 mma) =====
// kT: [kd=128][c 64] pitch 144; vT: [hd=256][c 64] pitch 144
#define KT_H 0
#define KT_L 18432
#define KVT_H 36864
#define KVT_L 73728
#define KV_SMEM 110592

__global__ void __launch_bounds__(256, 1)
kv_mma(const float* __restrict__ mask)
{
    extern __shared__ __align__(128) char sm[];
    const uint32_t sb = smem_u32(sm);
    const int tid = threadIdx.x;
    const int wid = tid >> 5, lane = tid & 31;
    const int wm = wid & 1, wn = wid >> 1;
    const int g = lane >> 2, q = lane & 3;
    const int chunk = blockIdx.x;
    const int b = chunk / (NC_*H_);
    const int n = (chunk / H_) % NC_;
    const int h = chunk % H_;
    const int lrow8 = (lane & 7) + ((lane >> 3) & 1) * 8;
    const int koffB = (lane >> 4) * 16;

    const float* ksrc = g_k + ((size_t)(b*T_ + n*CH_)) * E_ + h*KD_;
    const float* vsrc = g_v + ((size_t)(b*T_ + n*CH_)) * E2_ + h*HD_;
    const float* wrow = mask + (size_t)h * (CH_*CH_) + (size_t)(CH_-1) * CH_;

    float acc[4][8][4] = {};

    for (int sl = 0; sl < 4; sl++) {
        __syncthreads();
        // stage weighted k^T: [kd][cl]
        {
            const int cl = tid >> 2;
            const int kb_ = (tid & 3) * 32;
            const int c = sl * 64 + cl;
            const float w = wrow[c];
            const float* src = ksrc + (size_t)c * E_;
            #pragma unroll
            for (int p = 0; p < 8; p++) {
                const int kd = kb_ + p * 4;
                float4 u = *(const float4*)(src + kd);
                const float f[4] = {u.x * w, u.y * w, u.z * w, u.w * w};
                #pragma unroll
                for (int j = 0; j < 4; j++)
                    split_store16(sm + KT_H, sm + KT_L, kd + j, 144, cl, f[j]);
            }
        }
        // stage v^T: [hd][cl]
        {
            const int d_ = tid >> 6;
            const int c_ = (tid & 63) * 4;
            #pragma unroll
            for (int p = 0; p < 16; p++) {
                int dl = p * 4 + d_;
                int c = sl * 64 + dl;
                float4 u = *(const float4*)(vsrc + (size_t)c * E2_ + c_);
                const float f[4] = {u.x, u.y, u.z, u.w};
                #pragma unroll
                for (int j = 0; j < 4; j++)
                    split_store16(sm + KVT_H, sm + KVT_L, c_ + j, 144, dl, f[j]);
            }
        }
        __syncthreads();
        const uint32_t ao[3] = {KT_H, KT_H, KT_L};
        const uint32_t bo[3] = {KVT_H, KVT_L, KVT_H};
        #pragma unroll
        for (int ps = 0; ps < 3; ps++) {
            const uint32_t a_base = sb + ao[ps] + (uint32_t)((wm*64 + lrow8) * 144 + koffB);
            const uint32_t b_base = sb + bo[ps] + (uint32_t)((wn*64 + lrow8) * 144 + koffB);
            #pragma unroll
            for (int ks = 0; ks < 4; ks++) {
                const uint32_t kb = ks * 32;
                uint32_t af[4][4];
                #pragma unroll
                for (int mf = 0; mf < 4; mf++) ldm_x4(af[mf], a_base + mf * 16 * 144 + kb);
                uint32_t bf[8][2];
                #pragma unroll
                for (int nf2 = 0; nf2 < 4; nf2++) {
                    uint32_t t4[4];
                    ldm_x4(t4, b_base + nf2 * 16 * 144 + kb);
                    bf[2*nf2  ][0] = t4[0]; bf[2*nf2  ][1] = t4[2];
                    bf[2*nf2+1][0] = t4[1]; bf[2*nf2+1][1] = t4[3];
                }
                #pragma unroll
                for (int mf = 0; mf < 4; mf++)
                    #pragma unroll
                    for (int nf = 0; nf < 8; nf++)
                        mma_f16(acc[mf][nf], af[mf], bf[nf]);
            }
        }
    }

    float* op = g_kv + (size_t)chunk * (KD_*HD_);
    #pragma unroll
    for (int mf = 0; mf < 4; mf++) {
        const int r0 = wm*64 + mf*16 + g, r1 = r0 + 8;
        #pragma unroll
        for (int nf = 0; nf < 8; nf++) {
            const int c0 = wn*64 + nf*8 + q*2;
            *(float2*)(op + (size_t)r0 * HD_ + c0) = make_float2(acc[mf][nf][0], acc[mf][nf][1]);
            *(float2*)(op + (size_t)r1 * HD_ + c0) = make_float2(acc[mf][nf][2], acc[mf][nf][3]);
        }
    }
}

// ---------------- cross-chunk scan ----------------
__global__ __launch_bounds__(256)
void scan_kernel(const float* __restrict__ cdec)
{
    const int vb = blockIdx.x & 15;
    const int bh = blockIdx.x >> 4;
    const int b = bh / H_, h = bh % H_;
    const int v0 = vb * 16;
    const int tid = threadIdx.x;
    const int v = tid & 15;
    const int kg = tid >> 4;
    float s[8] = {0,0,0,0,0,0,0,0};
    __shared__ float sc[16];
    __shared__ float red[256];
    if (tid < 16) sc[tid] = 1.f;
    __syncthreads();
    const float cd = cdec[h];
    for (int n = 0; n < NC_; n++) {
        const int chunk = (b*NC_ + n)*H_ + h;
        const size_t zo = (size_t)chunk * (KD_*HD_);
        float invsc = 1.f / sc[v];
        #pragma unroll
        for (int i = 0; i < 8; i++)
            g_kvr[zo + (size_t)(kg*8+i)*HD_ + v0 + v] = s[i] * invsc;
        if (tid < 16) g_csc[chunk*HD_ + v0 + tid] = sc[tid];
        float p = 0.f;
        #pragma unroll
        for (int i = 0; i < 8; i++) {
            s[i] = s[i]*cd + g_kv[zo + (size_t)(kg*8+i)*HD_ + v0 + v];
            p += fabsf(s[i]);
        }
        red[tid] = p;
        __syncthreads();
        if (tid < 16) {
            float sum = 0.f;
            #pragma unroll
            for (int j = 0; j < 16; j++) sum += red[j*16 + tid];
            sc[tid] = fmaxf(sum, 1.f);
        }
        __syncthreads();
    }
}

// ===== cross = (qr*idec) @ kv_rec + combine + LN + silu gate (split-fp16) =====
// A: [r=128][kd=128] pitch 272 split; BT: [hd=256][kd 64] pitch 144 split
#define CA_H  0
#define CA_L  34816
#define CB_H  69632
#define CB_L  106496
#define CPART 143360     // 128 rows * 4 warps * 2 floats = 4096 B
#define CRCSC 147456     // 256 * 4 = 1024 B (1/csc)
#define CRISC 148480     // 128 * 4 = 512 B (1/clip(isc))
#define CROSS_SMEM 148992

__global__ void __launch_bounds__(256, 1)
cross_mma(const float* __restrict__ idec)
{
    extern __shared__ __align__(128) char sm[];
    const uint32_t sb = smem_u32(sm);
    const int tid = threadIdx.x;
    const int wid = tid >> 5, lane = tid & 31;
    const int wm = wid & 1, wn = wid >> 1;
    const int g = lane >> 2, q = lane & 3;
    const int z = blockIdx.x, chunk = z >> 1, hf = z & 1;
    const int b = chunk / (NC_*H_);
    const int n = (chunk / H_) % NC_;
    const int h = chunk % H_;
    const int row0 = hf * 128;
    const int lrow8 = (lane & 7) + ((lane >> 3) & 1) * 8;
    const int koffB = (lane >> 4) * 16;

    // scales -> SMEM (inverted)
    {
        float c = g_csc[chunk*HD_ + tid];
        ((float*)(sm + CRCSC))[tid] = 1.f / c;
        if (tid < 128) {
            float s = g_isc[chunk*CH_ + row0 + tid];
            ((float*)(sm + CRISC))[tid] = 1.f / fmaxf(s, 1.f);
        }
    }
    // stage A = qr * idec[r]
    {
        const float* qsrc = g_q + ((size_t)(b*T_ + n*CH_ + row0)) * E_ + h*KD_;
        const int r_ = tid >> 4, c_ = (tid & 15) * 8;
        #pragma unroll
        for (int p = 0; p < 8; p++) {
            int r = p * 16 + r_;
            float aw = idec[h*CH_ + row0 + r];
            float4 u0 = *(const float4*)(qsrc + (size_t)r * E_ + c_);
            float4 u1 = *(const float4*)(qsrc + (size_t)r * E_ + c_ + 4);
            u0.x *= aw; u0.y *= aw; u0.z *= aw; u0.w *= aw;
            u1.x *= aw; u1.y *= aw; u1.z *= aw; u1.w *= aw;
            uint4 hi, lo; split8(u0, u1, hi, lo);
            *(uint4*)(sm + CA_H + r * 272 + c_ * 2) = hi;
            *(uint4*)(sm + CA_L + r * 272 + c_ * 2) = lo;
        }
    }

    float acc[4][8][4] = {};
    const float* kvrsrc = g_kvr + (size_t)chunk * (KD_*HD_);

    for (int sl = 0; sl < 2; sl++) {
        __syncthreads();
        // stage kvr^T slab: [hd][kd 64]
        {
            const int d_ = tid >> 6;
            const int c_ = (tid & 63) * 4;
            #pragma unroll
            for (int p = 0; p < 16; p++) {
                int dl = p * 4 + d_;
                int kd = sl * 64 + dl;
                float4 u = *(const float4*)(kvrsrc + (size_t)kd * HD_ + c_);
                const float f[4] = {u.x, u.y, u.z, u.w};
                #pragma unroll
                for (int j = 0; j < 4; j++)
                    split_store16(sm + CB_H, sm + CB_L, c_ + j, 144, dl, f[j]);
            }
        }
        __syncthreads();
        const uint32_t ao[3] = {CA_H, CA_H, CA_L};
        const uint32_t bo[3] = {CB_H, CB_L, CB_H};
        #pragma unroll
        for (int ps = 0; ps < 3; ps++) {
            const uint32_t a_base = sb + ao[ps] + (uint32_t)((wm*64 + lrow8) * 272 + sl * 128 + koffB);
            const uint32_t b_base = sb + bo[ps] + (uint32_t)((wn*64 + lrow8) * 144 + koffB);
            #pragma unroll
            for (int ks = 0; ks < 4; ks++) {
                const uint32_t kb = ks * 32;
                uint32_t af[4][4];
                #pragma unroll
                for (int mf = 0; mf < 4; mf++) ldm_x4(af[mf], a_base + mf * 16 * 272 + kb);
                uint32_t bf[8][2];
                #pragma unroll
                for (int nf2 = 0; nf2 < 4; nf2++) {
                    uint32_t t4[4];
                    ldm_x4(t4, b_base + nf2 * 16 * 144 + kb);
                    bf[2*nf2  ][0] = t4[0]; bf[2*nf2  ][1] = t4[2];
                    bf[2*nf2+1][0] = t4[1]; bf[2*nf2+1][1] = t4[3];
                }
                #pragma unroll
                for (int mf = 0; mf < 4; mf++)
                    #pragma unroll
                    for (int nf = 0; nf < 8; nf++)
                        mma_f16(acc[mf][nf], af[mf], bf[nf]);
            }
        }
    }

    // combine with inner, row stats, LN + silu gate
    const float* innp = g_inner + (size_t)chunk * (CH_*HD_) + (size_t)row0 * HD_;
    const float* rcsc = (const float*)(sm + CRCSC);
    const float* risc = (const float*)(sm + CRISC);
    float* part = (float*)(sm + CPART);

    #pragma unroll
    for (int mf = 0; mf < 4; mf++) {
        const int r0 = wm*64 + mf*16 + g, r1 = r0 + 8;
        const float i0 = risc[r0], i1 = risc[r1];
        float s0 = 0.f, q0 = 0.f, s1 = 0.f, q1 = 0.f;
        #pragma unroll
        for (int nf = 0; nf < 8; nf++) {
            const int c0 = wn*64 + nf*8 + q*2;
            const float rc0 = rcsc[c0], rc1 = rcsc[c0+1];
            float2 in0 = *(const float2*)(innp + (size_t)r0 * HD_ + c0);
            float2 in1 = *(const float2*)(innp + (size_t)r1 * HD_ + c0);
            float o00 = in0.x * rc0 + acc[mf][nf][0] * i0;
            float o01 = in0.y * rc1 + acc[mf][nf][1] * i0;
            float o10 = in1.x * rc0 + acc[mf][nf][2] * i1;
            float o11 = in1.y * rc1 + acc[mf][nf][3] * i1;
            acc[mf][nf][0] = o00; acc[mf][nf][1] = o01;
            acc[mf][nf][2] = o10; acc[mf][nf][3] = o11;
            s0 += o00 + o01; q0 += o00*o00 + o01*o01;
            s1 += o10 + o11; q1 += o10*o10 + o11*o11;
        }
        s0 += __shfl_xor_sync(0xffffffffu, s0, 1); s0 += __shfl_xor_sync(0xffffffffu, s0, 2);
        q0 += __shfl_xor_sync(0xffffffffu, q0, 1); q0 += __shfl_xor_sync(0xffffffffu, q0, 2);
        s1 += __shfl_xor_sync(0xffffffffu, s1, 1); s1 += __shfl_xor_sync(0xffffffffu, s1, 2);
        q1 += __shfl_xor_sync(0xffffffffu, q1, 1); q1 += __shfl_xor_sync(0xffffffffu, q1, 2);
        if (q == 0) {
            part[(r0*4 + wn)*2    ] = s0;
            part[(r0*4 + wn)*2 + 1] = q0;
            part[(r1*4 + wn)*2    ] = s1;
            part[(r1*4 + wn)*2 + 1] = q1;
        }
    }
    __syncthreads();

    const float* gp = g_gt + ((size_t)(b*T_ + n*CH_ + row0)) * E2_ + h*HD_;
    __half* rop     = g_roh + ((size_t)(b*T_ + n*CH_ + row0)) * E2_ + h*HD_;
    #pragma unroll
    for (int mf = 0; mf < 4; mf++) {
        const int r0 = wm*64 + mf*16 + g, r1 = r0 + 8;
        float rs0 = part[(r0*4+0)*2] + part[(r0*4+1)*2] + part[(r0*4+2)*2] + part[(r0*4+3)*2];
        float rq0 = part[(r0*4+0)*2+1] + part[(r0*4+1)*2+1] + part[(r0*4+2)*2+1] + part[(r0*4+3)*2+1];
        float rs1 = part[(r1*4+0)*2] + part[(r1*4+1)*2] + part[(r1*4+2)*2] + part[(r1*4+3)*2];
        float rq1 = part[(r1*4+0)*2+1] + part[(r1*4+1)*2+1] + part[(r1*4+2)*2+1] + part[(r1*4+3)*2+1];
        const float mean0 = rs0 * (1.f/HD_);
        const float mean1 = rs1 * (1.f/HD_);
        const float rstd0 = rsqrtf(rq0 * (1.f/HD_) - mean0*mean0 + 1e-5f);
        const float rstd1 = rsqrtf(rq1 * (1.f/HD_) - mean1*mean1 + 1e-5f);
        #pragma unroll
        for (int nf = 0; nf < 8; nf++) {
            const int c0 = wn*64 + nf*8 + q*2;
            float gv00 = gp[(size_t)r0 * E2_ + c0],     gv01 = gp[(size_t)r0 * E2_ + c0 + 1];
            float gv10 = gp[(size_t)r1 * E2_ + c0],     gv11 = gp[(size_t)r1 * E2_ + c0 + 1];
            float o00 = (gv00 / (1.f + expf(-gv00))) * (acc[mf][nf][0] - mean0) * rstd0;
            float o01 = (gv01 / (1.f + expf(-gv01))) * (acc[mf][nf][1] - mean0) * rstd0;
            float o10 = (gv10 / (1.f + expf(-gv10))) * (acc[mf][nf][2] - mean1) * rstd1;
            float o11 = (gv11 / (1.f + expf(-gv11))) * (acc[mf][nf][3] - mean1) * rstd1;
            __half2 h0 = __floats2half2_rn(o00, o01);
            __half2 h1 = __floats2half2_rn(o10, o11);
            *(uint32_t*)(rop + (size_t)r0 * E2_ + c0) = *(uint32_t*)&h0;
            *(uint32_t*)(rop + (size_t)r1 * E2_ + c0) = *(uint32_t*)&h1;
        }
    }
}

// ================= launch =================
extern "C" void kernel_launch(void* const* d_in, const int* in_sizes, int n_in,
                              void* d_out, int out_size)
{
    const float* x    = (const float*)d_in[0];
    const float* sn   = (const float*)d_in[1];
    const float* cs   = (const float*)d_in[2];
    const float* mask = (const float*)d_in[3];
    const float* cdec = (const float*)d_in[4];
    const float* idec = (const float*)d_in[5];
    const float* Wq = (const float*)d_in[6];
    const float* bq = (const float*)d_in[7];
    const float* Wk = (const float*)d_in[8];
    const float* bk = (const float*)d_in[9];
    const float* Wv = (const float*)d_in[10];
    const float* bv = (const float*)d_in[11];
    const float* Wg = (const float*)d_in[12];
    const float* bg = (const float*)d_in[13];
    const float* Wo = (const float*)d_in[14];
    const float* bo = (const float*)d_in[15];
    float* out = (float*)d_out;

    float *qp, *kp, *vp, *gp;
    __half *xh, *roh, *wqh, *wkh, *wvh, *wgh, *woh;
    cudaGetSymbolAddress((void**)&qp,  g_q);
    cudaGetSymbolAddress((void**)&kp,  g_k);
    cudaGetSymbolAddress((void**)&vp,  g_v);
    cudaGetSymbolAddress((void**)&gp,  g_gt);
    cudaGetSymbolAddress((void**)&xh,  g_xh);
    cudaGetSymbolAddress((void**)&roh, g_roh);
    cudaGetSymbolAddress((void**)&wqh, g_wqh);
    cudaGetSymbolAddress((void**)&wkh, g_wkh);
    cudaGetSymbolAddress((void**)&wvh, g_wvh);
    cudaGetSymbolAddress((void**)&wgh, g_wgh);
    cudaGetSymbolAddress((void**)&woh, g_woh);

    cudaFuncSetAttribute(gemm_h, cudaFuncAttributeMaxDynamicSharedMemorySize, GEMMH_SMEM);
    cudaFuncSetAttribute(qki_kernel, cudaFuncAttributeMaxDynamicSharedMemorySize, QKI_SMEM);
    cudaFuncSetAttribute(kv_mma, cudaFuncAttributeMaxDynamicSharedMemorySize, KV_SMEM);
    cudaFuncSetAttribute(cross_mma, cudaFuncAttributeMaxDynamicSharedMemorySize, CROSS_SMEM);

    const int M = B_*T_;
    const float kscale = 1.0f / sqrtf((float)KD_);

    f2h<<<(M*E_/4 + 255)/256, 256>>>(x, xh, M*E_/4);
    f2h<<<(E_*E_/4 + 255)/256, 256>>>(Wq, wqh, E_*E_/4);
    f2h<<<(E_*E_/4 + 255)/256, 256>>>(Wk, wkh, E_*E_/4);
    f2h<<<(E2_*E_/4 + 255)/256, 256>>>(Wv, wvh, E2_*E_/4);
    f2h<<<(E2_*E_/4 + 255)/256, 256>>>(Wg, wgh, E2_*E_/4);
    f2h<<<(E_*E2_/4 + 255)/256, 256>>>(Wo, woh, E_*E2_/4);

    gemm_h<<<dim3(E_/128,  M/128), 256, GEMMH_SMEM>>>(xh, wqh, bq, qp, E_,  E_,  1.f);
    gemm_h<<<dim3(E_/128,  M/128), 256, GEMMH_SMEM>>>(xh, wkh, bk, kp, E_,  E_,  kscale);
    gemm_h<<<dim3(E2_/128, M/128), 256, GEMMH_SMEM>>>(xh, wvh, bv, vp, E_,  E2_, 1.f);
    gemm_h<<<dim3(E2_/128, M/128), 256, GEMMH_SMEM>>>(xh, wgh, bg, gp, E_,  E2_, 1.f);
    rotary_k<<<(B_*T_*E_/2 + 255)/256, 256>>>(qp, kp, sn, cs);
    qki_kernel<<<2*NCHUNKS, 256, QKI_SMEM>>>(mask);
    kv_mma    <<<NCHUNKS,   256, KV_SMEM>>>(mask);
    scan_kernel<<<B_*H_*(HD_/16), 256>>>(cdec);
    cross_mma <<<2*NCHUNKS, 256, CROSS_SMEM>>>(idec);
    gemm_h<<<dim3(E_/128, M/128), 256, GEMMH_SMEM>>>(roh, woh, bo, out, E2_, E_, 1.f);
}